// round 8
// baseline (speedup 1.0000x reference)
#include <cuda_runtime.h>
#include <cuda_bf16.h>

#define NE 8
#define TT 8192
#define HH 1024
#define II 4096

typedef unsigned int u32;

// ---- packed hi/lo bf16 planes, interleaved per 8-half chunk: hi@+0, lo@+8 halves ----
__device__ __nv_bfloat16 g_xp [(size_t)2 * TT * HH];
__device__ __nv_bfloat16 g_w1p[(size_t)2 * NE * HH * II];
__device__ __nv_bfloat16 g_w2p[(size_t)2 * NE * II * HH];
__device__ __nv_bfloat16 g_upp[(size_t)2 * TT * II];

// ---- smem stage layout (bf16 halves), BK = 32 k per stage ----
// Ahi [128][40], Alo [128][40], Bhi [32][136], Blo [32][136]
#define A_ROW 40
#define B_ROW 136
#define OFF_ALO (128 * A_ROW)                  // 5120
#define OFF_BHI (2 * 128 * A_ROW)              // 10240
#define OFF_BLO (OFF_BHI + 32 * B_ROW)         // 14592
#define STAGE_H (OFF_BHI + 2 * 32 * B_ROW)     // 18944 halves
#define STAGE_B (STAGE_H * 2)                  // 37888 bytes
#define NSTAGE  3
#define SMEM_BYTES (NSTAGE * STAGE_B)          // 113664

static __device__ __forceinline__ u32 smem_u32(const void* p) {
    u32 a;
    asm("{ .reg .u64 t; cvta.to.shared.u64 t, %1; cvt.u32.u64 %0, t; }" : "=r"(a) : "l"(p));
    return a;
}

#define CP16(dst, src) \
    asm volatile("cp.async.cg.shared.global [%0], [%1], 16;" :: "r"(dst), "l"(src))
#define CP_COMMIT() asm volatile("cp.async.commit_group;" ::: "memory")
#define CP_WAIT1()  asm volatile("cp.async.wait_group 1;" ::: "memory")

#define LDSM4(r, addr)                                                        \
    asm volatile("ldmatrix.sync.aligned.m8n8.x4.shared.b16 {%0,%1,%2,%3}, [%4];" \
                 : "=r"((r)[0]), "=r"((r)[1]), "=r"((r)[2]), "=r"((r)[3])     \
                 : "r"(addr))

#define LDSM4T(r, addr)                                                       \
    asm volatile("ldmatrix.sync.aligned.m8n8.x4.trans.shared.b16 {%0,%1,%2,%3}, [%4];" \
                 : "=r"((r)[0]), "=r"((r)[1]), "=r"((r)[2]), "=r"((r)[3])     \
                 : "r"(addr))

#define MMA16816(d, a, b0, b1)                                                \
    asm volatile("mma.sync.aligned.m16n8k16.row.col.f32.bf16.bf16.f32 "       \
                 "{%0,%1,%2,%3},{%4,%5,%6,%7},{%8,%9},{%0,%1,%2,%3};"         \
                 : "+f"((d)[0]), "+f"((d)[1]), "+f"((d)[2]), "+f"((d)[3])     \
                 : "r"((a)[0]), "r"((a)[1]), "r"((a)[2]), "r"((a)[3]),        \
                   "r"(b0), "r"(b1))

static __device__ __forceinline__ void cvt_hilo(float x, float y, u32& h, u32& l) {
    __nv_bfloat162 hb = __float22bfloat162_rn(make_float2(x, y));
    float2 hf = __bfloat1622float2(hb);
    __nv_bfloat162 lb = __float22bfloat162_rn(make_float2(x - hf.x, y - hf.y));
    h = *(u32*)&hb;
    l = *(u32*)&lb;
}

// fp32 -> packed hi/lo interleaved chunks; RL = row length (elements)
template <int RL>
__global__ __launch_bounds__(256)
void cvt_split(const float* __restrict__ src, __nv_bfloat16* __restrict__ dst, int nch)
{
    int c = blockIdx.x * 256 + threadIdx.x;
    if (c >= nch) return;
    const float4* s = (const float4*)(src + (size_t)c * 8);
    float4 v0 = s[0], v1 = s[1];
    u32 h0, l0, h1, l1, h2, l2, h3, l3;
    cvt_hilo(v0.x, v0.y, h0, l0); cvt_hilo(v0.z, v0.w, h1, l1);
    cvt_hilo(v1.x, v1.y, h2, l2); cvt_hilo(v1.z, v1.w, h3, l3);
    int row = c / (RL / 8), cc = c % (RL / 8);
    __nv_bfloat16* d = dst + (size_t)row * (2 * RL) + cc * 16;
    *(uint4*)d       = make_uint4(h0, h1, h2, h3);
    *(uint4*)(d + 8) = make_uint4(l0, l1, l2, l3);
}

// one stage of cp.async loads: 4 A chunks + 4 B chunks per thread
template <int K, int N>
static __device__ __forceinline__ void load_stage(u32 stA, u32 stB,
        const __nv_bfloat16* sa, const __nv_bfloat16* sb)
{
    CP16(stA,                                    sa);
    CP16(stA + 64 * A_ROW * 2,                   sa + (size_t)64 * 2 * K);
    CP16(stA + OFF_ALO * 2,                      sa + 8);
    CP16(stA + OFF_ALO * 2 + 64 * A_ROW * 2,     sa + (size_t)64 * 2 * K + 8);
    CP16(stB,                                    sb);
    CP16(stB + 16 * B_ROW * 2,                   sb + (size_t)16 * 2 * N);
    CP16(stB + (OFF_BLO - OFF_BHI) * 2,          sb + 8);
    CP16(stB + (OFF_BLO - OFF_BHI) * 2 + 16 * B_ROW * 2, sb + (size_t)16 * 2 * N + 8);
}

// C[row0:+128, n0:+128] = A[rows,:K] @ W[e,:K,n0:+128]; packed-plane operands.
// EPI=0: fp32 C.  EPI=1: packed hi/lo Up.
template <int K, int N, int EPI>
__global__ __launch_bounds__(256, 2)
void gemm_moe(const __nv_bfloat16* __restrict__ Ap, const __nv_bfloat16* __restrict__ Wp,
              const int* __restrict__ bsz, float* __restrict__ C,
              __nv_bfloat16* __restrict__ Up)
{
    extern __shared__ __nv_bfloat16 sm[];
    const u32 sbase = smem_u32(sm);
    const int tid = threadIdx.x;
    const int lane = tid & 31;
    const int wid = tid >> 5;
    const int warp_m = wid & 3;
    const int warp_n = wid >> 2;
    const int row0 = blockIdx.y * 128;
    const int n0 = blockIdx.x * 128;

    int cum = 0, e = 0;
#pragma unroll
    for (int i = 0; i < NE; i++) { if (row0 >= cum) e = i; cum += bsz[i]; }

    // ---- cp.async mappings (halves are the unit) ----
    const int ar = tid >> 2, ac = tid & 3;   // A: rows ar, ar+64 ; chunk ac of 4
    const int bk = tid >> 4, bc = tid & 15;  // B: rows bk, bk+16 ; chunk bc of 16
    const __nv_bfloat16* sa = Ap + (size_t)(row0 + ar) * (2 * K) + ac * 16;
    const __nv_bfloat16* sb = Wp + (size_t)e * (2 * (size_t)K * N)
                                 + (size_t)bk * (2 * N) + bc * 16 + 2 * n0;
    const u32 dA = sbase + (u32)((ar * A_ROW + ac * 8) * 2);
    const u32 dB = sbase + (u32)(OFF_BHI * 2 + (bk * B_ROW + bc * 8) * 2);

    // ---- ldmatrix lane bases (stage-relative bytes) ----
    const int a_r = lane & 15, a_c = (lane >> 4) * 8;
    const u32 aoff = (u32)(((warp_m * 32 + a_r) * A_ROW + a_c) * 2);
    const int b_k = (lane & 7) + 8 * ((lane >> 3) & 1);
    const int b_n = 8 * (lane >> 4);
    const u32 boff = (u32)((OFF_BHI + b_k * B_ROW + warp_n * 64 + b_n) * 2);

    float acc[2][8][4];
#pragma unroll
    for (int mf = 0; mf < 2; mf++)
#pragma unroll
        for (int nf = 0; nf < 8; nf++)
#pragma unroll
            for (int v = 0; v < 4; v++) acc[mf][nf][v] = 0.0f;

    const int NS = K >> 5;

    // ---- prologue: stages 0,1 ----
#pragma unroll
    for (int p = 0; p < NSTAGE - 1; p++) {
        load_stage<K, N>(dA + p * STAGE_B, dB + p * STAGE_B, sa, sb);
        CP_COMMIT();
        sa += 64;                 // 4 chunks = 64 halves along k
        sb += (size_t)64 * N;     // 32 k-rows = 64N halves
    }

    int sidx = 0;
    for (int s = 0; s < NS; s++) {
        CP_WAIT1();
        __syncthreads();

        if (s + 2 < NS) {
            int pidx = sidx + 2; if (pidx >= 3) pidx -= 3;
            load_stage<K, N>(dA + pidx * STAGE_B, dB + pidx * STAGE_B, sa, sb);
            sa += 64;
            sb += (size_t)64 * N;
        }
        CP_COMMIT();

        const u32 stb = (u32)(sidx * STAGE_B);
        sidx++; if (sidx >= 3) sidx -= 3;
        const u32 a_ld = sbase + stb + aoff;
        const u32 b_ld = sbase + stb + boff;

#pragma unroll
        for (int ki = 0; ki < 2; ki++) {
            const u32 ka = a_ld + ki * 32;                 // +16 halves along k
            const u32 kb = b_ld + ki * (16 * B_ROW * 2);   // +16 k-rows
            u32 ah[2][4], al[2][4], bf[4][4];
#pragma unroll
            for (int mf = 0; mf < 2; mf++) LDSM4(ah[mf], ka + mf * (16 * A_ROW * 2));
#pragma unroll
            for (int mf = 0; mf < 2; mf++) LDSM4(al[mf], ka + mf * (16 * A_ROW * 2) + OFF_ALO * 2);
#pragma unroll
            for (int j = 0; j < 4; j++) LDSM4T(bf[j], kb + j * 32);   // B hi
#pragma unroll
            for (int mf = 0; mf < 2; mf++)
#pragma unroll
                for (int j = 0; j < 4; j++) {
                    MMA16816(acc[mf][2 * j],     ah[mf], bf[j][0], bf[j][1]);
                    MMA16816(acc[mf][2 * j + 1], ah[mf], bf[j][2], bf[j][3]);
                }
#pragma unroll
            for (int mf = 0; mf < 2; mf++)
#pragma unroll
                for (int j = 0; j < 4; j++) {
                    MMA16816(acc[mf][2 * j],     al[mf], bf[j][0], bf[j][1]);
                    MMA16816(acc[mf][2 * j + 1], al[mf], bf[j][2], bf[j][3]);
                }
#pragma unroll
            for (int j = 0; j < 4; j++) LDSM4T(bf[j], kb + j * 32 + (OFF_BLO - OFF_BHI) * 2);
#pragma unroll
            for (int mf = 0; mf < 2; mf++)
#pragma unroll
                for (int j = 0; j < 4; j++) {
                    MMA16816(acc[mf][2 * j],     ah[mf], bf[j][0], bf[j][1]);
                    MMA16816(acc[mf][2 * j + 1], ah[mf], bf[j][2], bf[j][3]);
                }
        }
    }

    // ---- epilogue ----
#pragma unroll
    for (int mf = 0; mf < 2; mf++)
#pragma unroll
        for (int nf = 0; nf < 8; nf++) {
            int r = row0 + warp_m * 32 + mf * 16 + (lane >> 2);
            int c = n0 + warp_n * 64 + nf * 8 + (lane & 3) * 2;
            if (EPI == 0) {
                *(float2*)(C + (size_t)r * N + c) =
                    make_float2(acc[mf][nf][0], acc[mf][nf][1]);
                *(float2*)(C + (size_t)(r + 8) * N + c) =
                    make_float2(acc[mf][nf][2], acc[mf][nf][3]);
            } else {
                u32 h, l;
                size_t off = (size_t)r * (2 * N) + ((c >> 3) << 4) + (c & 7);
                cvt_hilo(acc[mf][nf][0], acc[mf][nf][1], h, l);
                *(u32*)(Up + off) = h;
                *(u32*)(Up + off + 8) = l;
                off += (size_t)8 * (2 * N);
                cvt_hilo(acc[mf][nf][2], acc[mf][nf][3], h, l);
                *(u32*)(Up + off) = h;
                *(u32*)(Up + off + 8) = l;
            }
        }
}

extern "C" void kernel_launch(void* const* d_in, const int* in_sizes, int n_in,
                              void* d_out, int out_size)
{
    const float* hiddens = (const float*)d_in[0];
    const int*   bsz     = (const int*)d_in[1];
    const float* w1      = (const float*)d_in[2];
    const float* w2      = (const float*)d_in[3];
    float*       out     = (float*)d_out;

    __nv_bfloat16 *xp, *w1p, *w2p, *upp;
    cudaGetSymbolAddress((void**)&xp,  g_xp);
    cudaGetSymbolAddress((void**)&w1p, g_w1p);
    cudaGetSymbolAddress((void**)&w2p, g_w2p);
    cudaGetSymbolAddress((void**)&upp, g_upp);

    cudaFuncSetAttribute(gemm_moe<1024, 4096, 1>, cudaFuncAttributeMaxDynamicSharedMemorySize, SMEM_BYTES);
    cudaFuncSetAttribute(gemm_moe<4096, 1024, 0>, cudaFuncAttributeMaxDynamicSharedMemorySize, SMEM_BYTES);

    {
        int nch = (TT * HH) / 8;
        cvt_split<HH><<<(nch + 255) / 256, 256>>>(hiddens, xp, nch);
    }
    {
        int nch = (NE * HH * II) / 8;
        cvt_split<II><<<(nch + 255) / 256, 256>>>(w1, w1p, nch);
        cvt_split<HH><<<(nch + 255) / 256, 256>>>(w2, w2p, nch);
    }

    // up = hiddens @ w1[e] : K=1024, N=4096 ; packed hi/lo output
    gemm_moe<1024, 4096, 1><<<dim3(II / 128, TT / 128), 256, SMEM_BYTES>>>(
        xp, w1p, bsz, nullptr, upp);
    // down = up @ w2[e] : K=4096, N=1024 ; fp32 output
    gemm_moe<4096, 1024, 0><<<dim3(HH / 128, TT / 128), 256, SMEM_BYTES>>>(
        upp, w2p, bsz, out, nullptr);
}

// round 10
// speedup vs baseline: 1.2956x; 1.2956x over previous
#include <cuda_runtime.h>
#include <cuda_bf16.h>

#define NE 8
#define TT 8192
#define HH 1024
#define II 4096

typedef unsigned int u32;

// ---- separate hi/lo bf16 planes ----
__device__ __nv_bfloat16 g_xh[(size_t)TT * HH],  g_xl[(size_t)TT * HH];
__device__ __nv_bfloat16 g_w1h[(size_t)NE * HH * II], g_w1l[(size_t)NE * HH * II];
__device__ __nv_bfloat16 g_w2h[(size_t)NE * II * HH], g_w2l[(size_t)NE * II * HH];
__device__ __nv_bfloat16 g_uph[(size_t)TT * II], g_upl[(size_t)TT * II];

// ---- smem stage (halves): Ahi/Alo [256][40], Bhi/Blo [32][136], BK = 32 ----
#define A_ROW 40
#define B_ROW 136
#define OFF_ALO (256 * A_ROW)                  // 10240
#define OFF_BHI (2 * 256 * A_ROW)              // 20480
#define OFF_BLO (OFF_BHI + 32 * B_ROW)         // 24832
#define STAGE_H (OFF_BHI + 2 * 32 * B_ROW)     // 29184 halves
#define STAGE_B (STAGE_H * 2)                  // 58368 bytes
#define NSTAGE  3
#define SMEM_BYTES (NSTAGE * STAGE_B)          // 175104

static __device__ __forceinline__ u32 smem_u32(const void* p) {
    u32 a;
    asm("{ .reg .u64 t; cvta.to.shared.u64 t, %1; cvt.u32.u64 %0, t; }" : "=r"(a) : "l"(p));
    return a;
}

#define CP16(dst, src) \
    asm volatile("cp.async.cg.shared.global [%0], [%1], 16;" :: "r"(dst), "l"(src))
#define CP_COMMIT() asm volatile("cp.async.commit_group;" ::: "memory")
#define CP_WAIT1()  asm volatile("cp.async.wait_group 1;" ::: "memory")

#define LDSM4(r, addr)                                                        \
    asm volatile("ldmatrix.sync.aligned.m8n8.x4.shared.b16 {%0,%1,%2,%3}, [%4];" \
                 : "=r"((r)[0]), "=r"((r)[1]), "=r"((r)[2]), "=r"((r)[3])     \
                 : "r"(addr))

#define LDSM4T(r, addr)                                                       \
    asm volatile("ldmatrix.sync.aligned.m8n8.x4.trans.shared.b16 {%0,%1,%2,%3}, [%4];" \
                 : "=r"((r)[0]), "=r"((r)[1]), "=r"((r)[2]), "=r"((r)[3])     \
                 : "r"(addr))

#define MMA16816(d, a, b0, b1)                                                \
    asm volatile("mma.sync.aligned.m16n8k16.row.col.f32.bf16.bf16.f32 "       \
                 "{%0,%1,%2,%3},{%4,%5,%6,%7},{%8,%9},{%0,%1,%2,%3};"         \
                 : "+f"((d)[0]), "+f"((d)[1]), "+f"((d)[2]), "+f"((d)[3])     \
                 : "r"((a)[0]), "r"((a)[1]), "r"((a)[2]), "r"((a)[3]),        \
                   "r"(b0), "r"(b1))

static __device__ __forceinline__ void cvt_hilo(float x, float y, u32& h, u32& l) {
    __nv_bfloat162 hb = __float22bfloat162_rn(make_float2(x, y));
    float2 hf = __bfloat1622float2(hb);
    __nv_bfloat162 lb = __float22bfloat162_rn(make_float2(x - hf.x, y - hf.y));
    h = *(u32*)&hb;
    l = *(u32*)&lb;
}

__global__ __launch_bounds__(256)
void cvt_split_k(const float4* __restrict__ src, uint2* __restrict__ h,
                 uint2* __restrict__ l, int n4)
{
    int i = blockIdx.x * 256 + threadIdx.x;
    if (i < n4) {
        float4 v = src[i];
        u32 h0, l0, h1, l1;
        cvt_hilo(v.x, v.y, h0, l0);
        cvt_hilo(v.z, v.w, h1, l1);
        h[i] = make_uint2(h0, h1);
        l[i] = make_uint2(l0, l1);
    }
}

// C[row0:+256, n0:+128] = A[rows,:K] @ W[e,:K,n0:+128]; plane operands.
// EPI=0: fp32 C.  EPI=1: hi/lo planes Ch/Cl.
template <int K, int N, int EPI>
__global__ __launch_bounds__(256, 1)
void gemm_moe(const __nv_bfloat16* __restrict__ Ah, const __nv_bfloat16* __restrict__ Al,
              const __nv_bfloat16* __restrict__ Wh, const __nv_bfloat16* __restrict__ Wl,
              const int* __restrict__ bsz, float* __restrict__ C,
              __nv_bfloat16* __restrict__ Ch, __nv_bfloat16* __restrict__ Cl)
{
    extern __shared__ __nv_bfloat16 sm[];
    const u32 sbase = smem_u32(sm);
    const int tid = threadIdx.x;
    const int lane = tid & 31;
    const int wid = tid >> 5;
    const int warp_m = wid & 3;    // 4 warps along m (64 rows each)
    const int warp_n = wid >> 2;   // 2 warps along n (64 cols each)
    const int row0 = blockIdx.y * 256;
    const int n0 = blockIdx.x * 128;

    int cum = 0, e = 0;
#pragma unroll
    for (int i = 0; i < NE; i++) { if (row0 >= cum) e = i; cum += bsz[i]; }
    const size_t woff = (size_t)e * (size_t)K * (size_t)N;

    // ---- cp.async mapping ----
    const int ar = tid >> 2, ac = tid & 3;   // A: rows ar+{0,64,128,192}, chunk ac
    const int bk = tid >> 4, bc = tid & 15;  // B: rows bk, bk+16, chunk bc
    const __nv_bfloat16* pAh = Ah + (size_t)(row0 + ar) * K + ac * 8;
    const __nv_bfloat16* pAl = Al + (size_t)(row0 + ar) * K + ac * 8;
    const __nv_bfloat16* pBh = Wh + woff + (size_t)bk * N + n0 + bc * 8;
    const __nv_bfloat16* pBl = Wl + woff + (size_t)bk * N + n0 + bc * 8;
    const u32 dA = sbase + (u32)((ar * A_ROW + ac * 8) * 2);
    const u32 dB = sbase + (u32)(OFF_BHI * 2 + (bk * B_ROW + bc * 8) * 2);

    // ---- ldmatrix lane bases (include sbase! round-9 bug was missing it) ----
    const int a_r = lane & 15, a_c = (lane >> 4) * 8;
    const u32 aoff = sbase + (u32)(((warp_m * 64 + a_r) * A_ROW + a_c) * 2);
    const int b_k = (lane & 7) + 8 * ((lane >> 3) & 1);
    const int b_n = 8 * (lane >> 4);
    const u32 boff = sbase + (u32)((OFF_BHI + b_k * B_ROW + warp_n * 64 + b_n) * 2);

    float acc[4][8][4];
#pragma unroll
    for (int mf = 0; mf < 4; mf++)
#pragma unroll
        for (int nf = 0; nf < 8; nf++)
#pragma unroll
            for (int v = 0; v < 4; v++) acc[mf][nf][v] = 0.0f;

    const int NS = K >> 5;

#define LOAD_STAGE(stoff)                                                     \
    do {                                                                      \
        const u32 _a = dA + (stoff);                                          \
        const u32 _b = dB + (stoff);                                          \
        CP16(_a,                        pAh);                                 \
        CP16(_a + 64  * A_ROW * 2,      pAh + (size_t)64  * K);               \
        CP16(_a + 128 * A_ROW * 2,      pAh + (size_t)128 * K);               \
        CP16(_a + 192 * A_ROW * 2,      pAh + (size_t)192 * K);               \
        CP16(_a + OFF_ALO * 2,                  pAl);                         \
        CP16(_a + OFF_ALO * 2 + 64  * A_ROW * 2, pAl + (size_t)64  * K);      \
        CP16(_a + OFF_ALO * 2 + 128 * A_ROW * 2, pAl + (size_t)128 * K);      \
        CP16(_a + OFF_ALO * 2 + 192 * A_ROW * 2, pAl + (size_t)192 * K);      \
        CP16(_b,                        pBh);                                 \
        CP16(_b + 16 * B_ROW * 2,       pBh + (size_t)16 * N);                \
        CP16(_b + (OFF_BLO - OFF_BHI) * 2,                  pBl);             \
        CP16(_b + (OFF_BLO - OFF_BHI) * 2 + 16 * B_ROW * 2, pBl + (size_t)16 * N); \
        pAh += 32; pAl += 32;                                                 \
        pBh += (size_t)32 * N; pBl += (size_t)32 * N;                         \
    } while (0)

    LOAD_STAGE(0);         CP_COMMIT();
    LOAD_STAGE(STAGE_B);   CP_COMMIT();

    int sidx = 0;
    for (int s = 0; s < NS; s++) {
        CP_WAIT1();
        __syncthreads();

        if (s + 2 < NS) {
            int pidx = sidx + 2; if (pidx >= 3) pidx -= 3;
            LOAD_STAGE((u32)(pidx * STAGE_B));
        }
        CP_COMMIT();

        const u32 stb = (u32)(sidx * STAGE_B);
        sidx++; if (sidx >= 3) sidx -= 3;
        const u32 a_ld = stb + aoff;   // aoff/boff carry sbase
        const u32 b_ld = stb + boff;

#pragma unroll
        for (int ki = 0; ki < 2; ki++) {
            const u32 ka = a_ld + ki * 32;                 // +16 halves along k
            const u32 kb = b_ld + ki * (16 * B_ROW * 2);   // +16 k-rows
            u32 ah[4][4], al[4][4], bf[4][4];
#pragma unroll
            for (int mf = 0; mf < 4; mf++) LDSM4(ah[mf], ka + mf * (16 * A_ROW * 2));
#pragma unroll
            for (int mf = 0; mf < 4; mf++) LDSM4(al[mf], ka + mf * (16 * A_ROW * 2) + OFF_ALO * 2);
#pragma unroll
            for (int j = 0; j < 4; j++) LDSM4T(bf[j], kb + j * 32);   // B hi
#pragma unroll
            for (int mf = 0; mf < 4; mf++)
#pragma unroll
                for (int j = 0; j < 4; j++) {
                    MMA16816(acc[mf][2 * j],     ah[mf], bf[j][0], bf[j][1]);
                    MMA16816(acc[mf][2 * j + 1], ah[mf], bf[j][2], bf[j][3]);
                }
#pragma unroll
            for (int mf = 0; mf < 4; mf++)
#pragma unroll
                for (int j = 0; j < 4; j++) {
                    MMA16816(acc[mf][2 * j],     al[mf], bf[j][0], bf[j][1]);
                    MMA16816(acc[mf][2 * j + 1], al[mf], bf[j][2], bf[j][3]);
                }
#pragma unroll
            for (int j = 0; j < 4; j++) LDSM4T(bf[j], kb + j * 32 + (OFF_BLO - OFF_BHI) * 2);
#pragma unroll
            for (int mf = 0; mf < 4; mf++)
#pragma unroll
                for (int j = 0; j < 4; j++) {
                    MMA16816(acc[mf][2 * j],     ah[mf], bf[j][0], bf[j][1]);
                    MMA16816(acc[mf][2 * j + 1], ah[mf], bf[j][2], bf[j][3]);
                }
        }
    }
#undef LOAD_STAGE

    // ---- epilogue ----
#pragma unroll
    for (int mf = 0; mf < 4; mf++)
#pragma unroll
        for (int nf = 0; nf < 8; nf++) {
            int r = row0 + warp_m * 64 + mf * 16 + (lane >> 2);
            int c = n0 + warp_n * 64 + nf * 8 + (lane & 3) * 2;
            if (EPI == 0) {
                *(float2*)(C + (size_t)r * N + c) =
                    make_float2(acc[mf][nf][0], acc[mf][nf][1]);
                *(float2*)(C + (size_t)(r + 8) * N + c) =
                    make_float2(acc[mf][nf][2], acc[mf][nf][3]);
            } else {
                u32 h, l;
                cvt_hilo(acc[mf][nf][0], acc[mf][nf][1], h, l);
                *(u32*)(Ch + (size_t)r * N + c) = h;
                *(u32*)(Cl + (size_t)r * N + c) = l;
                cvt_hilo(acc[mf][nf][2], acc[mf][nf][3], h, l);
                *(u32*)(Ch + (size_t)(r + 8) * N + c) = h;
                *(u32*)(Cl + (size_t)(r + 8) * N + c) = l;
            }
        }
}

extern "C" void kernel_launch(void* const* d_in, const int* in_sizes, int n_in,
                              void* d_out, int out_size)
{
    const float* hiddens = (const float*)d_in[0];
    const int*   bsz     = (const int*)d_in[1];
    const float* w1      = (const float*)d_in[2];
    const float* w2      = (const float*)d_in[3];
    float*       out     = (float*)d_out;

    __nv_bfloat16 *xh, *xl, *w1h, *w1l, *w2h, *w2l, *uph, *upl;
    cudaGetSymbolAddress((void**)&xh, g_xh);   cudaGetSymbolAddress((void**)&xl, g_xl);
    cudaGetSymbolAddress((void**)&w1h, g_w1h); cudaGetSymbolAddress((void**)&w1l, g_w1l);
    cudaGetSymbolAddress((void**)&w2h, g_w2h); cudaGetSymbolAddress((void**)&w2l, g_w2l);
    cudaGetSymbolAddress((void**)&uph, g_uph); cudaGetSymbolAddress((void**)&upl, g_upl);

    cudaFuncSetAttribute(gemm_moe<1024, 4096, 1>, cudaFuncAttributeMaxDynamicSharedMemorySize, SMEM_BYTES);
    cudaFuncSetAttribute(gemm_moe<4096, 1024, 0>, cudaFuncAttributeMaxDynamicSharedMemorySize, SMEM_BYTES);

    {
        int n4 = (TT * HH) / 4;
        cvt_split_k<<<(n4 + 255) / 256, 256>>>((const float4*)hiddens, (uint2*)xh, (uint2*)xl, n4);
    }
    {
        int n4 = (NE * HH * II) / 4;
        cvt_split_k<<<(n4 + 255) / 256, 256>>>((const float4*)w1, (uint2*)w1h, (uint2*)w1l, n4);
        cvt_split_k<<<(n4 + 255) / 256, 256>>>((const float4*)w2, (uint2*)w2h, (uint2*)w2l, n4);
    }

    // up = hiddens @ w1[e] : K=1024, N=4096 ; hi/lo plane output
    gemm_moe<1024, 4096, 1><<<dim3(II / 128, TT / 256), 256, SMEM_BYTES>>>(
        xh, xl, w1h, w1l, bsz, nullptr, uph, upl);
    // down = up @ w2[e] : K=4096, N=1024 ; fp32 output
    gemm_moe<4096, 1024, 0><<<dim3(HH / 128, TT / 256), 256, SMEM_BYTES>>>(
        uph, upl, w2h, w2l, bsz, out, nullptr, nullptr);
}